// round 14
// baseline (speedup 1.0000x reference)
#include <cuda_runtime.h>
#include <math.h>

#define SS  8192
#define IND 128
#define DD  64
#define NT  608            // 19 warps, each warp owns one position (all 8 batches)
#define WARPS (NT/32)

#define W_FLOATS (2*IND*DD + 5*DD*DD)          // 36864 floats static weights
#define STAGE_PER_WARP 1024                    // X input [b][128]; S (p-major) overlaps
#define SMEM_FLOATS (W_FLOATS + WARPS*STAGE_PER_WARP)
#define SMEM_BYTES  (SMEM_FLOATS*4)            // 225,280 B

typedef unsigned long long ull;

// phi table: phiT[s][j*64+i] = cos(2*pi*s/(i*64+j+2)), 128 MiB static
__device__ float g_phiT[SS * DD * DD];

// ---- packed f32x2 helpers (sm_100) ----
__device__ __forceinline__ ull dup2(float a){ ull r; asm("mov.b64 %0, {%1,%1};":"=l"(r):"f"(a)); return r; }
__device__ __forceinline__ ull pk2(float x,float y){ ull r; asm("mov.b64 %0, {%1,%2};":"=l"(r):"f"(x),"f"(y)); return r; }
__device__ __forceinline__ float2 up2(ull v){ float2 f; asm("mov.b64 {%0,%1}, %2;":"=f"(f.x),"=f"(f.y):"l"(v)); return f; }
__device__ __forceinline__ void fma2(ull&d, ull a, ull b){ asm("fma.rn.f32x2 %0, %1, %2, %0;":"+l"(d):"l"(a),"l"(b)); }
__device__ __forceinline__ ull mul2(ull a, ull b){ ull r; asm("mul.rn.f32x2 %0, %1, %2;":"=l"(r):"l"(a),"l"(b)); return r; }
__device__ __forceinline__ ull add2(ull a, ull b){ ull r; asm("add.rn.f32x2 %0, %1, %2;":"=l"(r):"l"(a),"l"(b)); return r; }
__device__ __forceinline__ ull shfl2(ull v, int o){
    float2 f = up2(v);
    f.x = __shfl_xor_sync(0xffffffffu, f.x, o);
    f.y = __shfl_xor_sync(0xffffffffu, f.y, o);
    return pk2(f.x, f.y);
}

// cos(2*pi*s/p) via exact integer mod (s,p integers < 2^14)
__device__ __forceinline__ float pcosf(float sf, float pf){
    float rp; asm("rcp.approx.f32 %0, %1;" : "=f"(rp) : "f"(pf));
    float q = rintf(sf * rp);
    float m = fmaf(q, -pf, sf);
    float v = m * rp;
    return __cosf(v * 6.28318530717958647692f);
}

// ---- kernel A: fill phi table (transposed [s][j*64+i]) ----
__global__ __launch_bounds__(256, 4)
void phi_fill(void){
    const int s = blockIdx.x;
    const float sf = (float)s;
    float* row = g_phiT + (size_t)s * (DD*DD);
#pragma unroll
    for (int u = 0; u < (DD*DD)/256; u++){
        int idx = u*256 + threadIdx.x;     // idx = j*64 + i
        int i = idx & 63, j = idx >> 6;
        row[idx] = pcosf(sf, (float)(i*DD + j + 2));
    }
}

// Batch-packed LayerNorm (shfl2 ladders)
__device__ __forceinline__ void ln8bp(ull a0[4], ull a1[4],
                                      float ga, float gb, float ba, float bb){
    ull s[4];
#pragma unroll
    for (int p=0;p<4;p++) s[p] = add2(a0[p], a1[p]);
#pragma unroll
    for (int o=16;o;o>>=1){
#pragma unroll
        for (int p=0;p<4;p++) s[p] = add2(s[p], shfl2(s[p], o));
    }
    const ull negi = dup2(-0.015625f);
    ull q[4];
#pragma unroll
    for (int p=0;p<4;p++){
        ull nm = mul2(s[p], negi);
        a0[p] = add2(a0[p], nm);
        a1[p] = add2(a1[p], nm);
        q[p] = mul2(a0[p], a0[p]);
        fma2(q[p], a1[p], a1[p]);
    }
#pragma unroll
    for (int o=16;o;o>>=1){
#pragma unroll
        for (int p=0;p<4;p++) q[p] = add2(q[p], shfl2(q[p], o));
    }
    const ull gd0 = dup2(ga), gd1 = dup2(gb), bd0 = dup2(ba), bd1 = dup2(bb);
#pragma unroll
    for (int p=0;p<4;p++){
        float2 v = up2(q[p]);
        float r0 = rsqrtf(fmaf(v.x, 0.015625f, 1e-5f));
        float r1 = rsqrtf(fmaf(v.y, 0.015625f, 1e-5f));
        ull rs = pk2(r0, r1);
        ull t0 = mul2(a0[p], rs), t1 = mul2(a1[p], rs);
        a0[p] = bd0; fma2(a0[p], t0, gd0);
        a1[p] = bd1; fma2(a1[p], t1, gd1);
    }
}

// S layout: p-major. Row p (batch pair p) holds 64 ull (j = 0..63) at
// S + p*128 floats. (p,j) = one ull. 16B-aligned, conflict-free stores.

// Batch-packed 64x64 matvec: one bcast LDS.128 per (j-pair, p).
__device__ __forceinline__ void mm64bp(const float* __restrict__ Wt,
                                       const float* __restrict__ S,
                                       int l2, ull acc0[4], ull acc1[4]){
#pragma unroll 4
    for (int j2=0;j2<32;j2++){
        float2 wa = up2(*(const ull*)(Wt + (2*j2)*DD + l2));
        float2 wb = up2(*(const ull*)(Wt + (2*j2+1)*DD + l2));
        ull d00=dup2(wa.x), d01=dup2(wa.y), d10=dup2(wb.x), d11=dup2(wb.y);
#pragma unroll
        for (int p=0;p<4;p++){
            ulonglong2 v = ((const ulonglong2*)(S + p*128))[j2];  // rows j, j+1
            fma2(acc0[p], d00, v.x);  fma2(acc1[p], d01, v.x);
            fma2(acc0[p], d10, v.y);  fma2(acc1[p], d11, v.y);
        }
    }
}

// Batch-packed phase matvec using the precomputed phi table.
__device__ __forceinline__ void nmv64bp(const float* __restrict__ Pt,
                                        const float* __restrict__ phis,
                                        const float* __restrict__ S,
                                        int l2, ull acc0[4], ull acc1[4]){
#pragma unroll 4
    for (int j2=0;j2<32;j2++){
        ull f0 = *(const ull*)(phis + (2*j2)*DD + l2);
        ull f1 = *(const ull*)(phis + (2*j2+1)*DD + l2);
        float2 wa = up2(mul2(*(const ull*)(Pt + (2*j2)*DD + l2), f0));
        float2 wb = up2(mul2(*(const ull*)(Pt + (2*j2+1)*DD + l2), f1));
        ull d00=dup2(wa.x), d01=dup2(wa.y), d10=dup2(wb.x), d11=dup2(wb.y);
#pragma unroll
        for (int p=0;p<4;p++){
            ulonglong2 v = ((const ulonglong2*)(S + p*128))[j2];
            fma2(acc0[p], d00, v.x);  fma2(acc1[p], d01, v.x);
            fma2(acc0[p], d10, v.y);  fma2(acc1[p], d11, v.y);
        }
    }
}

// store batch-packed rows (2l, 2l+1) into p-major S: 4 contiguous STS.128
__device__ __forceinline__ void store_bp(float* S, int l, const ull y0[4], const ull y1[4]){
#pragma unroll
    for (int p=0;p<4;p++){
        ulonglong2 t; t.x = y0[p]; t.y = y1[p];
        ((ulonglong2*)(S + p*128))[l] = t;
    }
}

__global__ __launch_bounds__(NT, 1)
void hier_fused7(const float* __restrict__ seq,
                 const float* __restrict__ M1, const float* __restrict__ P1,
                 const float* __restrict__ g1, const float* __restrict__ b1,
                 const float* __restrict__ Wr1,
                 const float* __restrict__ M2, const float* __restrict__ P2,
                 const float* __restrict__ g2, const float* __restrict__ b2,
                 const float* __restrict__ M3, const float* __restrict__ P3,
                 const float* __restrict__ g3, const float* __restrict__ b3,
                 float* __restrict__ out)
{
    extern __shared__ float sm[];
    float* sM1T = sm;                    // [j][i] 128x64
    float* sWrT = sM1T + IND*DD;         // 128x64
    float* sM2T = sWrT + IND*DD;         // 64x64 each
    float* sM3T = sM2T + DD*DD;
    float* sP1T = sM3T + DD*DD;
    float* sP2T = sP1T + DD*DD;
    float* sP3T = sP2T + DD*DD;
    float* stage = sP3T + DD*DD;

    const int tid = threadIdx.x;
    const int wid = tid >> 5;
    const int l   = tid & 31;
    const int l2  = 2*l;

    float* X = stage + wid*STAGE_PER_WARP;   // [b][128] input (layer 1 only)
    float* S = X;                            // p-major staging (512 floats), reused

    // ---- preload weights transposed into SMEM ----
    for (int idx = tid; idx < IND*DD; idx += NT){
        int i = idx >> 7, j = idx & 127;
        sM1T[j*DD + i] = M1[idx];
        sWrT[j*DD + i] = Wr1[idx];
    }
    for (int idx = tid; idx < DD*DD; idx += NT){
        int i = idx >> 6, j = idx & 63;
        sM2T[j*DD + i] = M2[idx];
        sM3T[j*DD + i] = M3[idx];
        sP1T[j*DD + i] = P1[idx];
        sP2T[j*DD + i] = P2[idx];
        sP3T[j*DD + i] = P3[idx];
    }
    const float G1a=g1[l2], G1b=g1[l2+1], B1a=b1[l2], B1b=b1[l2+1];
    const float G2a=g2[l2], G2b=g2[l2+1], B2a=b2[l2], B2b=b2[l2+1];
    const float G3a=g3[l2], G3b=g3[l2+1], B3a=b3[l2], B3b=b3[l2+1];
    __syncthreads();

    const int stride = gridDim.x * WARPS;

    for (int s = blockIdx.x*WARPS + wid; s < SS; s += stride){
        const float* phis = g_phiT + (size_t)s * (DD*DD);

        // ---- load input (8 batches x 128) into staging ----
#pragma unroll
        for (int b=0;b<8;b++){
            float4 v = *(const float4*)(seq + ((size_t)b*SS + s)*IND + 4*l);
            *(float4*)(X + b*IND + 4*l) = v;
        }
        __syncwarp();

        // ====== layer 1: xt = x@M1T, rr = x@WrT (i-packed per batch) ======
        ull xt[8], rr[8];
#pragma unroll
        for (int b=0;b<8;b++){ xt[b]=0ull; rr[b]=0ull; }
#pragma unroll 1
        for (int j=0;j<IND;j+=4){
            ull m0 = *(const ull*)(sM1T + j*DD + l2);
            ull m1 = *(const ull*)(sM1T + (j+1)*DD + l2);
            ull m2 = *(const ull*)(sM1T + (j+2)*DD + l2);
            ull m3 = *(const ull*)(sM1T + (j+3)*DD + l2);
            ull r0 = *(const ull*)(sWrT + j*DD + l2);
            ull r1 = *(const ull*)(sWrT + (j+1)*DD + l2);
            ull r2 = *(const ull*)(sWrT + (j+2)*DD + l2);
            ull r3 = *(const ull*)(sWrT + (j+3)*DD + l2);
#pragma unroll
            for (int b=0;b<8;b++){
                float4 av = *(const float4*)(X + b*IND + j);   // bcast LDS.128
                ull a0 = dup2(av.x), a1 = dup2(av.y), a2 = dup2(av.z), a3 = dup2(av.w);
                fma2(xt[b], m0, a0);  fma2(rr[b], r0, a0);
                fma2(xt[b], m1, a1);  fma2(rr[b], r1, a1);
                fma2(xt[b], m2, a2);  fma2(rr[b], r2, a2);
                fma2(xt[b], m3, a3);  fma2(rr[b], r3, a3);
            }
        }
        // transpose to batch-packed: {x}t0[bp] = row i0 for batches (2bp,2bp+1)
        ull xt0[4], xt1[4], rr0[4], rr1[4];
#pragma unroll
        for (int p=0;p<4;p++){
            float2 e = up2(xt[2*p]), f = up2(xt[2*p+1]);
            xt0[p] = pk2(e.x, f.x);  xt1[p] = pk2(e.y, f.y);
            float2 u = up2(rr[2*p]), v = up2(rr[2*p+1]);
            rr0[p] = pk2(u.x, v.x);  rr1[p] = pk2(u.y, v.y);
        }
        ln8bp(xt0, xt1, G1a, G1b, B1a, B1b);
        __syncwarp();                       // X reads complete before S overwrite
        store_bp(S, l, xt0, xt1);
        __syncwarp();
        ull z0[4], z1[4];
#pragma unroll
        for (int p=0;p<4;p++){ z0[p]=0ull; z1[p]=0ull; }
        nmv64bp(sP1T, phis, S, l2, z0, z1);
#pragma unroll
        for (int p=0;p<4;p++){ z0[p]=add2(z0[p],rr0[p]); z1[p]=add2(z1[p],rr1[p]); }

        // ====== layer 2 ======
        __syncwarp();
        store_bp(S, l, z0, z1);
        __syncwarp();
#pragma unroll
        for (int p=0;p<4;p++){ xt0[p]=0ull; xt1[p]=0ull; }
        mm64bp(sM2T, S, l2, xt0, xt1);
        ln8bp(xt0, xt1, G2a, G2b, B2a, B2b);
        __syncwarp();
        store_bp(S, l, xt0, xt1);
        __syncwarp();
        ull nn0[4], nn1[4];
#pragma unroll
        for (int p=0;p<4;p++){ nn0[p]=0ull; nn1[p]=0ull; }
        nmv64bp(sP2T, phis, S, l2, nn0, nn1);
#pragma unroll
        for (int p=0;p<4;p++){ z0[p]=add2(nn0[p],z0[p]); z1[p]=add2(nn1[p],z1[p]); }

        // ====== layer 3 ======
        __syncwarp();
        store_bp(S, l, z0, z1);
        __syncwarp();
#pragma unroll
        for (int p=0;p<4;p++){ xt0[p]=0ull; xt1[p]=0ull; }
        mm64bp(sM3T, S, l2, xt0, xt1);
        ln8bp(xt0, xt1, G3a, G3b, B3a, B3b);
        __syncwarp();
        store_bp(S, l, xt0, xt1);
        __syncwarp();
#pragma unroll
        for (int p=0;p<4;p++){ nn0[p]=0ull; nn1[p]=0ull; }
        nmv64bp(sP3T, phis, S, l2, nn0, nn1);
#pragma unroll
        for (int p=0;p<4;p++){ z0[p]=add2(nn0[p],z0[p]); z1[p]=add2(nn1[p],z1[p]); }

        // ---- transpose back to i-packed and store (8 x STG.64) ----
#pragma unroll
        for (int p=0;p<4;p++){
            float2 a = up2(z0[p]), b = up2(z1[p]);
            *(ull*)(out + ((size_t)(2*p)*SS   + s)*DD + l2) = pk2(a.x, b.x);
            *(ull*)(out + ((size_t)(2*p+1)*SS + s)*DD + l2) = pk2(a.y, b.y);
        }
    }
}

extern "C" void kernel_launch(void* const* d_in, const int* in_sizes, int n_in,
                              void* d_out, int out_size) {
    const float* seq = (const float*)d_in[0];
    const float* M1  = (const float*)d_in[1];
    const float* P1  = (const float*)d_in[2];
    const float* g1  = (const float*)d_in[3];
    const float* b1  = (const float*)d_in[4];
    const float* Wr1 = (const float*)d_in[5];
    const float* M2  = (const float*)d_in[6];
    const float* P2  = (const float*)d_in[7];
    const float* g2  = (const float*)d_in[8];
    const float* b2  = (const float*)d_in[9];
    const float* M3  = (const float*)d_in[10];
    const float* P3  = (const float*)d_in[11];
    const float* g3  = (const float*)d_in[12];
    const float* b3  = (const float*)d_in[13];
    float* out = (float*)d_out;

    cudaFuncSetAttribute(hier_fused7,
                         cudaFuncAttributeMaxDynamicSharedMemorySize, SMEM_BYTES);

    int dev = 0, sms = 148;
    if (cudaGetDevice(&dev) == cudaSuccess) {
        int v = 0;
        if (cudaDeviceGetAttribute(&v, cudaDevAttrMultiProcessorCount, dev) == cudaSuccess
            && v > 0) sms = v;
    }

    phi_fill<<<SS, 256>>>();
    hier_fused7<<<sms, NT, SMEM_BYTES>>>(seq, M1, P1, g1, b1, Wr1,
                                         M2, P2, g2, b2, M3, P3, g3, b3, out);
}

// round 15
// speedup vs baseline: 1.0252x; 1.0252x over previous
#include <cuda_runtime.h>
#include <math.h>

#define SS  8192
#define IND 128
#define DD  64
#define NT  608            // 19 warps, each warp owns one position (all 8 batches)
#define WARPS (NT/32)

#define W_FLOATS (2*IND*DD + 5*DD*DD)          // 36864 floats static weights
#define STAGE_PER_WARP 1024                    // X input [b][128]; S (p-major) overlaps
#define SMEM_FLOATS (W_FLOATS + WARPS*STAGE_PER_WARP)
#define SMEM_BYTES  (SMEM_FLOATS*4)            // 225,280 B

typedef unsigned long long ull;

// phi table: phiT[s][j*64+i] = cos(2*pi*s/(i*64+j+2)), 128 MiB static
__device__ float g_phiT[SS * DD * DD];

// ---- packed f32x2 helpers (sm_100) ----
__device__ __forceinline__ ull dup2(float a){ ull r; asm("mov.b64 %0, {%1,%1};":"=l"(r):"f"(a)); return r; }
__device__ __forceinline__ ull pk2(float x,float y){ ull r; asm("mov.b64 %0, {%1,%2};":"=l"(r):"f"(x),"f"(y)); return r; }
__device__ __forceinline__ float2 up2(ull v){ float2 f; asm("mov.b64 {%0,%1}, %2;":"=f"(f.x),"=f"(f.y):"l"(v)); return f; }
__device__ __forceinline__ void fma2(ull&d, ull a, ull b){ asm("fma.rn.f32x2 %0, %1, %2, %0;":"+l"(d):"l"(a),"l"(b)); }
__device__ __forceinline__ ull mul2(ull a, ull b){ ull r; asm("mul.rn.f32x2 %0, %1, %2;":"=l"(r):"l"(a),"l"(b)); return r; }
__device__ __forceinline__ ull add2(ull a, ull b){ ull r; asm("add.rn.f32x2 %0, %1, %2;":"=l"(r):"l"(a),"l"(b)); return r; }
__device__ __forceinline__ ull shfl2(ull v, int o){
    float2 f = up2(v);
    f.x = __shfl_xor_sync(0xffffffffu, f.x, o);
    f.y = __shfl_xor_sync(0xffffffffu, f.y, o);
    return pk2(f.x, f.y);
}

// cos(2*pi*s/p) via exact integer mod (s,p integers < 2^14)
__device__ __forceinline__ float pcosf(float sf, float pf){
    float rp; asm("rcp.approx.f32 %0, %1;" : "=f"(rp) : "f"(pf));
    float q = rintf(sf * rp);
    float m = fmaf(q, -pf, sf);
    float v = m * rp;
    return __cosf(v * 6.28318530717958647692f);
}

// ---- kernel A: fill phi table (transposed [s][j*64+i]) ----
__global__ __launch_bounds__(256, 4)
void phi_fill(void){
    const int s = blockIdx.x;
    const float sf = (float)s;
    float* row = g_phiT + (size_t)s * (DD*DD);
#pragma unroll
    for (int u = 0; u < (DD*DD)/256; u++){
        int idx = u*256 + threadIdx.x;     // idx = j*64 + i
        int i = idx & 63, j = idx >> 6;
        row[idx] = pcosf(sf, (float)(i*DD + j + 2));
    }
}

// Batch-packed LayerNorm (shfl2 ladders)
__device__ __forceinline__ void ln8bp(ull a0[4], ull a1[4],
                                      float ga, float gb, float ba, float bb){
    ull s[4];
#pragma unroll
    for (int p=0;p<4;p++) s[p] = add2(a0[p], a1[p]);
#pragma unroll
    for (int o=16;o;o>>=1){
#pragma unroll
        for (int p=0;p<4;p++) s[p] = add2(s[p], shfl2(s[p], o));
    }
    const ull negi = dup2(-0.015625f);
    ull q[4];
#pragma unroll
    for (int p=0;p<4;p++){
        ull nm = mul2(s[p], negi);
        a0[p] = add2(a0[p], nm);
        a1[p] = add2(a1[p], nm);
        q[p] = mul2(a0[p], a0[p]);
        fma2(q[p], a1[p], a1[p]);
    }
#pragma unroll
    for (int o=16;o;o>>=1){
#pragma unroll
        for (int p=0;p<4;p++) q[p] = add2(q[p], shfl2(q[p], o));
    }
    const ull gd0 = dup2(ga), gd1 = dup2(gb), bd0 = dup2(ba), bd1 = dup2(bb);
#pragma unroll
    for (int p=0;p<4;p++){
        float2 v = up2(q[p]);
        float r0 = rsqrtf(fmaf(v.x, 0.015625f, 1e-5f));
        float r1 = rsqrtf(fmaf(v.y, 0.015625f, 1e-5f));
        ull rs = pk2(r0, r1);
        ull t0 = mul2(a0[p], rs), t1 = mul2(a1[p], rs);
        a0[p] = bd0; fma2(a0[p], t0, gd0);
        a1[p] = bd1; fma2(a1[p], t1, gd1);
    }
}

// S layout: p-major. Row p (batch pair p) holds 64 ull (j = 0..63) at
// S + p*128 floats. (p,j) = one ull. 16B-aligned, conflict-free stores.

// Batch-packed 64x64 matvec: one bcast LDS.128 per (j-pair, p).
__device__ __forceinline__ void mm64bp(const float* __restrict__ Wt,
                                       const float* __restrict__ S,
                                       int l2, ull acc0[4], ull acc1[4]){
#pragma unroll 4
    for (int j2=0;j2<32;j2++){
        float2 wa = up2(*(const ull*)(Wt + (2*j2)*DD + l2));
        float2 wb = up2(*(const ull*)(Wt + (2*j2+1)*DD + l2));
        ull d00=dup2(wa.x), d01=dup2(wa.y), d10=dup2(wb.x), d11=dup2(wb.y);
#pragma unroll
        for (int p=0;p<4;p++){
            ulonglong2 v = ((const ulonglong2*)(S + p*128))[j2];  // rows j, j+1
            fma2(acc0[p], d00, v.x);  fma2(acc1[p], d01, v.x);
            fma2(acc0[p], d10, v.y);  fma2(acc1[p], d11, v.y);
        }
    }
}

// Batch-packed phase matvec using the precomputed phi table.
__device__ __forceinline__ void nmv64bp(const float* __restrict__ Pt,
                                        const float* __restrict__ phis,
                                        const float* __restrict__ S,
                                        int l2, ull acc0[4], ull acc1[4]){
#pragma unroll 4
    for (int j2=0;j2<32;j2++){
        ull f0 = *(const ull*)(phis + (2*j2)*DD + l2);
        ull f1 = *(const ull*)(phis + (2*j2+1)*DD + l2);
        float2 wa = up2(mul2(*(const ull*)(Pt + (2*j2)*DD + l2), f0));
        float2 wb = up2(mul2(*(const ull*)(Pt + (2*j2+1)*DD + l2), f1));
        ull d00=dup2(wa.x), d01=dup2(wa.y), d10=dup2(wb.x), d11=dup2(wb.y);
#pragma unroll
        for (int p=0;p<4;p++){
            ulonglong2 v = ((const ulonglong2*)(S + p*128))[j2];
            fma2(acc0[p], d00, v.x);  fma2(acc1[p], d01, v.x);
            fma2(acc0[p], d10, v.y);  fma2(acc1[p], d11, v.y);
        }
    }
}

// store batch-packed rows (2l, 2l+1) into p-major S: 4 contiguous STS.128
__device__ __forceinline__ void store_bp(float* S, int l, const ull y0[4], const ull y1[4]){
#pragma unroll
    for (int p=0;p<4;p++){
        ulonglong2 t; t.x = y0[p]; t.y = y1[p];
        ((ulonglong2*)(S + p*128))[l] = t;
    }
}

__global__ __launch_bounds__(NT, 1)
void hier_fused8(const float* __restrict__ seq,
                 const float* __restrict__ M1, const float* __restrict__ P1,
                 const float* __restrict__ g1, const float* __restrict__ b1,
                 const float* __restrict__ Wr1,
                 const float* __restrict__ M2, const float* __restrict__ P2,
                 const float* __restrict__ g2, const float* __restrict__ b2,
                 const float* __restrict__ M3, const float* __restrict__ P3,
                 const float* __restrict__ g3, const float* __restrict__ b3,
                 float* __restrict__ out)
{
    extern __shared__ float sm[];
    float* sM1T = sm;                    // [j][i] 128x64
    float* sWrT = sM1T + IND*DD;         // 128x64
    float* sM2T = sWrT + IND*DD;         // 64x64 each
    float* sM3T = sM2T + DD*DD;
    float* sP1T = sM3T + DD*DD;
    float* sP2T = sP1T + DD*DD;
    float* sP3T = sP2T + DD*DD;
    float* stage = sP3T + DD*DD;

    const int tid = threadIdx.x;
    const int wid = tid >> 5;
    const int l   = tid & 31;
    const int l2  = 2*l;

    float* X = stage + wid*STAGE_PER_WARP;   // [b][128] input (layer 1 only)
    float* S = X;                            // p-major staging (512 floats), reused

    // ---- preload weights transposed into SMEM ----
    for (int idx = tid; idx < IND*DD; idx += NT){
        int i = idx >> 7, j = idx & 127;
        sM1T[j*DD + i] = M1[idx];
        sWrT[j*DD + i] = Wr1[idx];
    }
    for (int idx = tid; idx < DD*DD; idx += NT){
        int i = idx >> 6, j = idx & 63;
        sM2T[j*DD + i] = M2[idx];
        sM3T[j*DD + i] = M3[idx];
        sP1T[j*DD + i] = P1[idx];
        sP2T[j*DD + i] = P2[idx];
        sP3T[j*DD + i] = P3[idx];
    }
    const float G1a=g1[l2], G1b=g1[l2+1], B1a=b1[l2], B1b=b1[l2+1];
    const float G2a=g2[l2], G2b=g2[l2+1], B2a=b2[l2], B2b=b2[l2+1];
    const float G3a=g3[l2], G3b=g3[l2+1], B3a=b3[l2], B3b=b3[l2+1];
    __syncthreads();

    const int stride = gridDim.x * WARPS;

    for (int s = blockIdx.x*WARPS + wid; s < SS; s += stride){
        const float* phis = g_phiT + (size_t)s * (DD*DD);

        // ---- prefetch this position's phi row (16 KB) toward L2 so the
        //      nmv LDGs after layer 1 don't eat cold DRAM latency ----
#pragma unroll
        for (int u = 0; u < 4; u++)
            asm volatile("prefetch.global.L2 [%0];"
                         :: "l"(phis + (u*32 + l) * 32) : "memory");

        // ---- load input (8 batches x 128) into staging ----
#pragma unroll
        for (int b=0;b<8;b++){
            float4 v = *(const float4*)(seq + ((size_t)b*SS + s)*IND + 4*l);
            *(float4*)(X + b*IND + 4*l) = v;
        }
        __syncwarp();

        // ====== layer 1: xt = x@M1T, rr = x@WrT (i-packed per batch) ======
        ull xt[8], rr[8];
#pragma unroll
        for (int b=0;b<8;b++){ xt[b]=0ull; rr[b]=0ull; }
#pragma unroll 1
        for (int j=0;j<IND;j+=4){
            ull m0 = *(const ull*)(sM1T + j*DD + l2);
            ull m1 = *(const ull*)(sM1T + (j+1)*DD + l2);
            ull m2 = *(const ull*)(sM1T + (j+2)*DD + l2);
            ull m3 = *(const ull*)(sM1T + (j+3)*DD + l2);
            ull r0 = *(const ull*)(sWrT + j*DD + l2);
            ull r1 = *(const ull*)(sWrT + (j+1)*DD + l2);
            ull r2 = *(const ull*)(sWrT + (j+2)*DD + l2);
            ull r3 = *(const ull*)(sWrT + (j+3)*DD + l2);
#pragma unroll
            for (int b=0;b<8;b++){
                float4 av = *(const float4*)(X + b*IND + j);   // bcast LDS.128
                ull a0 = dup2(av.x), a1 = dup2(av.y), a2 = dup2(av.z), a3 = dup2(av.w);
                fma2(xt[b], m0, a0);  fma2(rr[b], r0, a0);
                fma2(xt[b], m1, a1);  fma2(rr[b], r1, a1);
                fma2(xt[b], m2, a2);  fma2(rr[b], r2, a2);
                fma2(xt[b], m3, a3);  fma2(rr[b], r3, a3);
            }
        }
        // transpose to batch-packed: {x}t0[bp] = row i0 for batches (2bp,2bp+1)
        ull xt0[4], xt1[4], rr0[4], rr1[4];
#pragma unroll
        for (int p=0;p<4;p++){
            float2 e = up2(xt[2*p]), f = up2(xt[2*p+1]);
            xt0[p] = pk2(e.x, f.x);  xt1[p] = pk2(e.y, f.y);
            float2 u = up2(rr[2*p]), v = up2(rr[2*p+1]);
            rr0[p] = pk2(u.x, v.x);  rr1[p] = pk2(u.y, v.y);
        }
        ln8bp(xt0, xt1, G1a, G1b, B1a, B1b);
        __syncwarp();                       // X reads complete before S overwrite
        store_bp(S, l, xt0, xt1);
        __syncwarp();
        ull z0[4], z1[4];
#pragma unroll
        for (int p=0;p<4;p++){ z0[p]=0ull; z1[p]=0ull; }
        nmv64bp(sP1T, phis, S, l2, z0, z1);
#pragma unroll
        for (int p=0;p<4;p++){ z0[p]=add2(z0[p],rr0[p]); z1[p]=add2(z1[p],rr1[p]); }

        // ====== layer 2 ======
        __syncwarp();
        store_bp(S, l, z0, z1);
        __syncwarp();
#pragma unroll
        for (int p=0;p<4;p++){ xt0[p]=0ull; xt1[p]=0ull; }
        mm64bp(sM2T, S, l2, xt0, xt1);
        ln8bp(xt0, xt1, G2a, G2b, B2a, B2b);
        __syncwarp();
        store_bp(S, l, xt0, xt1);
        __syncwarp();
        ull nn0[4], nn1[4];
#pragma unroll
        for (int p=0;p<4;p++){ nn0[p]=0ull; nn1[p]=0ull; }
        nmv64bp(sP2T, phis, S, l2, nn0, nn1);
#pragma unroll
        for (int p=0;p<4;p++){ z0[p]=add2(nn0[p],z0[p]); z1[p]=add2(nn1[p],z1[p]); }

        // ====== layer 3 ======
        __syncwarp();
        store_bp(S, l, z0, z1);
        __syncwarp();
#pragma unroll
        for (int p=0;p<4;p++){ xt0[p]=0ull; xt1[p]=0ull; }
        mm64bp(sM3T, S, l2, xt0, xt1);
        ln8bp(xt0, xt1, G3a, G3b, B3a, B3b);
        __syncwarp();
        store_bp(S, l, xt0, xt1);
        __syncwarp();
#pragma unroll
        for (int p=0;p<4;p++){ nn0[p]=0ull; nn1[p]=0ull; }
        nmv64bp(sP3T, phis, S, l2, nn0, nn1);
#pragma unroll
        for (int p=0;p<4;p++){ z0[p]=add2(nn0[p],z0[p]); z1[p]=add2(nn1[p],z1[p]); }

        // ---- transpose back to i-packed and store (8 x STG.64) ----
#pragma unroll
        for (int p=0;p<4;p++){
            float2 a = up2(z0[p]), b = up2(z1[p]);
            *(ull*)(out + ((size_t)(2*p)*SS   + s)*DD + l2) = pk2(a.x, b.x);
            *(ull*)(out + ((size_t)(2*p+1)*SS + s)*DD + l2) = pk2(a.y, b.y);
        }
    }
}

extern "C" void kernel_launch(void* const* d_in, const int* in_sizes, int n_in,
                              void* d_out, int out_size) {
    const float* seq = (const float*)d_in[0];
    const float* M1  = (const float*)d_in[1];
    const float* P1  = (const float*)d_in[2];
    const float* g1  = (const float*)d_in[3];
    const float* b1  = (const float*)d_in[4];
    const float* Wr1 = (const float*)d_in[5];
    const float* M2  = (const float*)d_in[6];
    const float* P2  = (const float*)d_in[7];
    const float* g2  = (const float*)d_in[8];
    const float* b2  = (const float*)d_in[9];
    const float* M3  = (const float*)d_in[10];
    const float* P3  = (const float*)d_in[11];
    const float* g3  = (const float*)d_in[12];
    const float* b3  = (const float*)d_in[13];
    float* out = (float*)d_out;

    cudaFuncSetAttribute(hier_fused8,
                         cudaFuncAttributeMaxDynamicSharedMemorySize, SMEM_BYTES);

    int dev = 0, sms = 148;
    if (cudaGetDevice(&dev) == cudaSuccess) {
        int v = 0;
        if (cudaDeviceGetAttribute(&v, cudaDevAttrMultiProcessorCount, dev) == cudaSuccess
            && v > 0) sms = v;
    }

    phi_fill<<<SS, 256>>>();
    hier_fused8<<<sms, NT, SMEM_BYTES>>>(seq, M1, P1, g1, b1, Wr1,
                                         M2, P2, g2, b2, M3, P3, g3, b3, out);
}